// round 1
// baseline (speedup 1.0000x reference)
#include <cuda_runtime.h>
#include <cuda_bf16.h>

// Problem constants
#define NB   16
#define NCIN 64
#define H1   128    // conv_pre input/output spatial
#define H2   256    // conv_post input/output spatial (after 2x upsample)
#define Q1   64     // quads for conv_pre: channels {q, q+64, q+128, q+192}
#define Q2   16     // quads for conv_post: channels {4q..4q+3}

// Tiling
#define TH   64
#define TW   32
#define CC   4      // cin per smem chunk
#define TWP  36     // padded smem row stride (TW+2 -> 36 to dodge conflicts)

// Scratch (allocation-free rule: __device__ globals)
__device__ float  g_up[(size_t)NB * NCIN * H2 * H2];          // 256 MB intermediate
__device__ float4 g_wpre [Q1 * NCIN * 9];                     // [q][cin][k] -> (ll,lh,hl,hh) weights
__device__ float4 g_wpost[Q2 * NCIN * 9];                     // [q][cin][k] -> (4q..4q+3) weights

// ---------------------------------------------------------------------------
// Weight reorder: pack the 4 channels of each quad into a float4 per tap so
// the conv inner loop does one LDS.128 per (cin, tap).
// ---------------------------------------------------------------------------
__global__ void reorder_pre(const float* __restrict__ w) {
    int i = blockIdx.x * blockDim.x + threadIdx.x;      // over Q1*NCIN*9
    if (i >= Q1 * NCIN * 9) return;
    int k   = i % 9;
    int cin = (i / 9) % NCIN;
    int q   = i / (9 * NCIN);
    float4 v;
    v.x = w[(((q        ) * NCIN + cin) * 9) + k];
    v.y = w[(((q +  64  ) * NCIN + cin) * 9) + k];
    v.z = w[(((q + 128  ) * NCIN + cin) * 9) + k];
    v.w = w[(((q + 192  ) * NCIN + cin) * 9) + k];
    g_wpre[i] = v;
}

__global__ void reorder_post(const float* __restrict__ w) {
    int i = blockIdx.x * blockDim.x + threadIdx.x;      // over Q2*NCIN*9
    if (i >= Q2 * NCIN * 9) return;
    int k   = i % 9;
    int cin = (i / 9) % NCIN;
    int q   = i / (9 * NCIN);
    float4 v;
    v.x = w[(((4*q + 0) * NCIN + cin) * 9) + k];
    v.y = w[(((4*q + 1) * NCIN + cin) * 9) + k];
    v.z = w[(((4*q + 2) * NCIN + cin) * 9) + k];
    v.w = w[(((4*q + 3) * NCIN + cin) * 9) + k];
    g_wpost[i] = v;
}

// ---------------------------------------------------------------------------
// Tiled direct 3x3 conv. Each block: one (b, quad), 64x32 spatial tile.
// Each thread: 2 rows x 4 cols x 4 channels = 32 fp32 accumulators.
// WAVELET=true : input = xp, epilogue = wavelet recombine + 2x shuffle -> g_up
// WAVELET=false: input = g_up, epilogue = plain NCHW store -> outp
// ---------------------------------------------------------------------------
template<int HIN, int Q, bool WAVELET>
__global__ __launch_bounds__(256, 2)
void conv3x3_q(const float* __restrict__ xp,
               const float* __restrict__ bias,
               float* __restrict__ outp)
{
    constexpr int WIN = HIN;
    __shared__ float  sIn[CC][TH + 2][TWP];
    __shared__ float4 sW[NCIN * 9];

    const int tid = threadIdx.x;
    const int wt  = blockIdx.x;
    const int ht  = blockIdx.y;
    const int z   = blockIdx.z;
    const int b   = z / Q;
    const int q   = z % Q;
    const int h0  = ht * TH;
    const int w0b = wt * TW;

    // weights for this quad -> smem
    const float4* wg = (WAVELET ? g_wpre : g_wpost) + q * NCIN * 9;
    for (int i = tid; i < NCIN * 9; i += 256) sW[i] = wg[i];

    const int rp = tid >> 3;      // row-pair 0..31  (out rows 2rp, 2rp+1)
    const int ws = tid & 7;       // w segment 0..7  (out cols 4ws..4ws+3)

    float bvv[4];
    if (WAVELET) {
        bvv[0] = bias[q];       bvv[1] = bias[q + 64];
        bvv[2] = bias[q + 128]; bvv[3] = bias[q + 192];
    } else {
        bvv[0] = bias[4*q + 0]; bvv[1] = bias[4*q + 1];
        bvv[2] = bias[4*q + 2]; bvv[3] = bias[4*q + 3];
    }

    float acc[2][4][4];
    #pragma unroll
    for (int r = 0; r < 2; ++r)
        #pragma unroll
        for (int p = 0; p < 4; ++p)
            #pragma unroll
            for (int c = 0; c < 4; ++c)
                acc[r][p][c] = bvv[c];

    const float* x = WAVELET ? xp : g_up;
    const float* xb = x + (size_t)b * NCIN * HIN * WIN;

    for (int cc = 0; cc < NCIN / CC; ++cc) {
        __syncthreads();
        // load CC input channels, (TH+2)x(TW+2) padded tile, zero-fill OOB
        constexpr int NLD = CC * (TH + 2) * (TW + 2);
        for (int i = tid; i < NLD; i += 256) {
            int col = i % (TW + 2);
            int t2  = i / (TW + 2);
            int r   = t2 % (TH + 2);
            int ci  = t2 / (TH + 2);
            int gh  = h0  - 1 + r;
            int gw  = w0b - 1 + col;
            float v = 0.0f;
            if (gh >= 0 && gh < HIN && gw >= 0 && gw < WIN)
                v = __ldg(&xb[(size_t)(cc * CC + ci) * HIN * WIN + (size_t)gh * WIN + gw]);
            sIn[ci][r][col] = v;
        }
        __syncthreads();

        #pragma unroll
        for (int ci = 0; ci < CC; ++ci) {
            float4 wk[9];
            #pragma unroll
            for (int k = 0; k < 9; ++k)
                wk[k] = sW[(cc * CC + ci) * 9 + k];

            const int baseR = rp * 2;
            #pragma unroll
            for (int j = 0; j < 4; ++j) {       // padded input rows baseR..baseR+3
                float xv[6];
                #pragma unroll
                for (int u = 0; u < 6; ++u)
                    xv[u] = sIn[ci][baseR + j][ws * 4 + u];

                #pragma unroll
                for (int kw = 0; kw < 3; ++kw) {
                    if (j <= 2) {               // contributes to out row 0 with kh=j
                        float4 wv = wk[j * 3 + kw];
                        #pragma unroll
                        for (int p = 0; p < 4; ++p) {
                            float xs = xv[p + kw];
                            acc[0][p][0] += xs * wv.x;
                            acc[0][p][1] += xs * wv.y;
                            acc[0][p][2] += xs * wv.z;
                            acc[0][p][3] += xs * wv.w;
                        }
                    }
                    if (j >= 1) {               // contributes to out row 1 with kh=j-1
                        float4 wv = wk[(j - 1) * 3 + kw];
                        #pragma unroll
                        for (int p = 0; p < 4; ++p) {
                            float xs = xv[p + kw];
                            acc[1][p][0] += xs * wv.x;
                            acc[1][p][1] += xs * wv.y;
                            acc[1][p][2] += xs * wv.z;
                            acc[1][p][3] += xs * wv.w;
                        }
                    }
                }
            }
        }
    }

    // ------------------------- epilogue -------------------------
    const int orow = h0  + rp * 2;
    const int ocol = w0b + ws * 4;

    if (WAVELET) {
        // t channels (ll,lh,hl,hh) -> 2x2 up block
        float* up = g_up + (size_t)(b * NCIN + q) * (2 * HIN) * (2 * WIN);
        #pragma unroll
        for (int rr = 0; rr < 2; ++rr) {
            int gh = orow + rr;
            #pragma unroll
            for (int p = 0; p < 4; ++p) {
                float ll = acc[rr][p][0], lh = acc[rr][p][1];
                float hl = acc[rr][p][2], hh = acc[rr][p][3];
                float ee = 0.5f * (ll + lh + hl + hh);
                float eo = 0.5f * (ll - lh + hl - hh);
                float oe = 0.5f * (ll + lh - hl - hh);
                float oo = 0.5f * (ll - lh - hl + hh);
                int gw = ocol + p;
                *(float2*)&up[(size_t)(2 * gh    ) * (2 * WIN) + 2 * gw] = make_float2(ee, eo);
                *(float2*)&up[(size_t)(2 * gh + 1) * (2 * WIN) + 2 * gw] = make_float2(oe, oo);
            }
        }
    } else {
        // plain NCHW store, one float4 per (row, channel)
        #pragma unroll
        for (int rr = 0; rr < 2; ++rr) {
            int gh = orow + rr;
            #pragma unroll
            for (int c = 0; c < 4; ++c) {
                float4 v = make_float4(acc[rr][0][c], acc[rr][1][c],
                                       acc[rr][2][c], acc[rr][3][c]);
                *(float4*)&outp[(size_t)(b * (4 * Q) + 4 * q + c) * HIN * WIN
                                + (size_t)gh * WIN + ocol] = v;
            }
        }
    }
}

extern "C" void kernel_launch(void* const* d_in, const int* in_sizes, int n_in,
                              void* d_out, int out_size)
{
    (void)in_sizes; (void)n_in; (void)out_size;
    const float* x      = (const float*)d_in[0];
    const float* w_pre  = (const float*)d_in[1];
    const float* b_pre  = (const float*)d_in[2];
    const float* w_post = (const float*)d_in[3];
    const float* b_post = (const float*)d_in[4];
    float* out = (float*)d_out;

    reorder_pre <<<(Q1 * NCIN * 9 + 255) / 256, 256>>>(w_pre);
    reorder_post<<<(Q2 * NCIN * 9 + 255) / 256, 256>>>(w_post);

    // conv_pre + wavelet upsample -> g_up
    {
        dim3 grid(H1 / TW, H1 / TH, NB * Q1);   // (4, 2, 1024)
        conv3x3_q<H1, Q1, true><<<grid, 256>>>(x, b_pre, nullptr);
    }
    // conv_post: g_up -> out
    {
        dim3 grid(H2 / TW, H2 / TH, NB * Q2);   // (8, 4, 256)
        conv3x3_q<H2, Q2, false><<<grid, 256>>>(nullptr, b_post, out);
    }
}